// round 10
// baseline (speedup 1.0000x reference)
#include <cuda_runtime.h>
#include <cstdint>

// ---------------------------------------------------------------------------
// FPNAttentionV2: fused conv1x1 batches + conv3x3/s2, BHWC outputs.
// TF32 mma.sync m16n8k8 (tcgen05 unavailable: harness ptxas targets sm_103
// without the 'a' feature set).
//
// conv1x1: cp.async double-buffered pipeline, ONE __syncthreads per kt.
//   X tile: plain [k][px] layout, row stride 136 words -> 16B cp.async chunks
//           (no transpose, no regs), scalar A-frag LDS conflict-free (8tg+gp).
//   W tile: kperm layout (k%4)*8+k/4, stride 36 -> LDS.128 B-frags (as R6).
//   X is fed raw f32 (mma tf32 truncates); W keeps cvt.rna.
// conv3x3: unchanged from the 382us baseline.
// ---------------------------------------------------------------------------

#define CC 256
#define PAD 36
#define XSTR 136                       // X tile row stride (words)
#define XTILE (32 * XSTR)              // 4352 words
#define WTILE (128 * PAD)              // 4608 words
#define SMEM1 ((2 * XTILE + 2 * WTILE) * 4)  // 71680 B

__device__ __forceinline__ uint32_t f2tf32(float f) {
    uint32_t r;
    asm("cvt.rna.tf32.f32 %0, %1;" : "=r"(r) : "f"(f));
    return r;
}

__device__ __forceinline__ void mma_tf32(float* c, const uint32_t* a, const uint32_t* b) {
    asm volatile(
        "mma.sync.aligned.m16n8k8.row.col.f32.tf32.tf32.f32 "
        "{%0,%1,%2,%3}, {%4,%5,%6,%7}, {%8,%9}, {%0,%1,%2,%3};"
        : "+f"(c[0]), "+f"(c[1]), "+f"(c[2]), "+f"(c[3])
        : "r"(a[0]), "r"(a[1]), "r"(a[2]), "r"(a[3]), "r"(b[0]), "r"(b[1]));
}

__device__ __forceinline__ void cp16(uint32_t sdst, const void* gsrc) {
    asm volatile("cp.async.cg.shared.global [%0], [%1], 16;"
                 :: "r"(sdst), "l"(gsrc) : "memory");
}
__device__ __forceinline__ void cp_commit() {
    asm volatile("cp.async.commit_group;" ::: "memory");
}
__device__ __forceinline__ void cp_wait0() {
    asm volatile("cp.async.wait_group 0;" ::: "memory");
}

struct ConvSet {
    const float* w[4];
    const float* b[4];
    float* out[4];
};

// ---- hybrid MMA phase: A scalar frags from X[k][px]; B uint4 from W kperm --
__device__ __forceinline__ void mma_hybrid(
    const uint32_t* __restrict__ X, const uint32_t* __restrict__ W,
    float (*acc)[4], int wm, int wn, int tg, int gp) {
#pragma unroll
    for (int h = 0; h < 2; ++h) {
        uint4 bf[8];
#pragma unroll
        for (int nt = 0; nt < 8; ++nt) {
            int col = wn * 64 + nt * 8 + gp;
            bf[nt] = *reinterpret_cast<const uint4*>(&W[col * PAD + tg * 8 + h * 4]);
        }
#pragma unroll
        for (int s = 0; s < 2; ++s) {
            const int kb = 16 * h + 8 * s;
#pragma unroll
            for (int mt = 0; mt < 2; ++mt) {
                const int row = wm * 32 + mt * 16 + gp;
                uint32_t a[4];
                a[0] = X[(kb + tg) * XSTR + row];
                a[1] = X[(kb + tg) * XSTR + row + 8];
                a[2] = X[(kb + tg + 4) * XSTR + row];
                a[3] = X[(kb + tg + 4) * XSTR + row + 8];
#pragma unroll
                for (int nt = 0; nt < 8; ++nt) {
                    const uint32_t* bw = reinterpret_cast<const uint32_t*>(&bf[nt]);
                    uint32_t bq[2] = {bw[2 * s], bw[2 * s + 1]};
                    mma_tf32(acc[mt * 8 + nt], a, bq);
                }
            }
        }
    }
}

// UPS: conv id whose output is 2x nearest-upsampled, or -1.
// grid: (HW/128, nconv*2, B); blockIdx.y = conv*2 + ochHalf. 256 threads.
template <int UPS>
__global__ __launch_bounds__(256, 2) void conv1x1_cp(
    const float* __restrict__ x, ConvSet cs, int HW) {
    extern __shared__ uint32_t sm[];
    uint32_t* Xb[2] = {sm, sm + XTILE};
    uint32_t* Wb[2] = {sm + 2 * XTILE, sm + 2 * XTILE + WTILE};

    const int tid  = threadIdx.x;
    const int lane = tid & 31;
    const int warp = tid >> 5;
    const int wm = warp >> 1, wn = warp & 1;
    const int tg = lane & 3, gp = lane >> 2;

    const int pt  = blockIdx.x * 128;
    const int cid = blockIdx.y >> 1;
    const int ot  = (blockIdx.y & 1) * 128;
    const int bb  = blockIdx.z;

    const float* xb   = x + (size_t)bb * CC * HW;
    const float* wptr = cs.w[cid];
    const float* bptr = cs.b[cid];
    float* out        = cs.out[cid];

    // X async loader coords: thread -> (c row, 64B span)
    const int xr_ = tid >> 3;        // 0..31
    const int xc_ = (tid & 7) * 16;  // float offset in row
    // W loader coords (R6 scheme)
    const int wo = tid >> 3;         // 0..31
    const int cq = tid & 7;

    float acc[16][4];
#pragma unroll
    for (int i = 0; i < 16; ++i)
#pragma unroll
        for (int j = 0; j < 4; ++j) acc[i][j] = 0.f;

    auto ldX = [&](int kt, uint32_t* Xd) {
        const float* src = xb + (size_t)(kt * 32 + xr_) * HW + pt + xc_;
        uint32_t sdst = (uint32_t)__cvta_generic_to_shared(Xd + xr_ * XSTR + xc_);
#pragma unroll
        for (int j = 0; j < 4; ++j) cp16(sdst + j * 16, src + j * 4);
        cp_commit();
    };
    auto ldW = [&](int kt, uint32_t* Wd) {
#pragma unroll
        for (int j = 0; j < 4; ++j) {
            int o = j * 32 + wo;
            float4 v = *reinterpret_cast<const float4*>(
                wptr + (size_t)(ot + o) * CC + kt * 32 + cq * 4);
            Wd[o * PAD + 0 + cq]  = f2tf32(v.x);
            Wd[o * PAD + 8 + cq]  = f2tf32(v.y);
            Wd[o * PAD + 16 + cq] = f2tf32(v.z);
            Wd[o * PAD + 24 + cq] = f2tf32(v.w);
        }
    };

    // prologue
    ldX(0, Xb[0]);
    ldW(0, Wb[0]);
    cp_wait0();
    __syncthreads();

    for (int kt = 0; kt < 8; ++kt) {
        const int cur = kt & 1, nxt = cur ^ 1;
        if (kt < 7) {
            ldX(kt + 1, Xb[nxt]);   // async, no regs, latency covered by MMA
            ldW(kt + 1, Wb[nxt]);   // small, L2-hot
        }
        mma_hybrid(Xb[cur], Wb[cur], acc, wm, wn, tg, gp);
        if (kt < 7) cp_wait0();
        __syncthreads();
    }

    // ---- epilogue: bias + BHWC store ----
#pragma unroll
    for (int nt = 0; nt < 8; ++nt) {
        int o = ot + wn * 64 + nt * 8 + tg * 2;
        float b0 = __ldg(&bptr[o]);
        float b1 = __ldg(&bptr[o + 1]);
#pragma unroll
        for (int mt = 0; mt < 2; ++mt) {
#pragma unroll
            for (int hr = 0; hr < 2; ++hr) {
                int pg = pt + wm * 32 + mt * 16 + gp + hr * 8;
                float2 r;
                r.x = acc[mt * 8 + nt][hr * 2 + 0] + b0;
                r.y = acc[mt * 8 + nt][hr * 2 + 1] + b1;
                if (UPS >= 0 && cid == UPS) {
                    int hh = pg >> 6, wc = pg & 63;
                    float* base = out +
                        ((size_t)bb * 16384 + (size_t)(2 * hh) * 128 + 2 * wc) * CC + o;
                    *reinterpret_cast<float2*>(base) = r;
                    *reinterpret_cast<float2*>(base + CC) = r;
                    *reinterpret_cast<float2*>(base + 128 * CC) = r;
                    *reinterpret_cast<float2*>(base + 128 * CC + CC) = r;
                } else {
                    *reinterpret_cast<float2*>(out + ((size_t)bb * HW + pg) * CC + o) = r;
                }
            }
        }
    }
}

// ---------------------------------------------------------------------------
// conv3x3/s2 — unchanged from the 382us baseline (known good).
// ---------------------------------------------------------------------------
template <int NT>
__device__ __forceinline__ void mma_phase(
    const uint32_t* __restrict__ Xp, const uint32_t* __restrict__ Wp,
    float (*acc)[4], int wm, int wn, int tg, int gp) {
#pragma unroll
    for (int h = 0; h < 2; ++h) {
        uint4 af[2][2], bf[NT];
#pragma unroll
        for (int mt = 0; mt < 2; ++mt) {
            int row = wm * 32 + mt * 16 + gp;
            af[mt][0] = *reinterpret_cast<const uint4*>(&Xp[row * PAD + tg * 8 + h * 4]);
            af[mt][1] = *reinterpret_cast<const uint4*>(&Xp[(row + 8) * PAD + tg * 8 + h * 4]);
        }
#pragma unroll
        for (int nt = 0; nt < NT; ++nt) {
            int col = wn * (NT * 8) + nt * 8 + gp;
            bf[nt] = *reinterpret_cast<const uint4*>(&Wp[col * PAD + tg * 8 + h * 4]);
        }
#pragma unroll
        for (int s = 0; s < 2; ++s) {
#pragma unroll
            for (int mt = 0; mt < 2; ++mt) {
                const uint32_t* a0 = reinterpret_cast<const uint32_t*>(&af[mt][0]);
                const uint32_t* a1 = reinterpret_cast<const uint32_t*>(&af[mt][1]);
                uint32_t a[4] = {a0[2 * s], a1[2 * s], a0[2 * s + 1], a1[2 * s + 1]};
#pragma unroll
                for (int nt = 0; nt < NT; ++nt) {
                    const uint32_t* bw = reinterpret_cast<const uint32_t*>(&bf[nt]);
                    uint32_t bq[2] = {bw[2 * s], bw[2 * s + 1]};
                    mma_tf32(acc[mt * NT + nt], a, bq);
                }
            }
        }
    }
}

__global__ __launch_bounds__(256, 2) void conv3x3s2_kernel(
    const float* __restrict__ x, const float* __restrict__ w,
    const float* __restrict__ bias, float* __restrict__ out) {
    __shared__ uint32_t Xs[128 * PAD];
    __shared__ uint32_t Ws[64 * PAD];

    const int tid  = threadIdx.x;
    const int lane = tid & 31;
    const int warp = tid >> 5;
    const int wm = warp >> 1, wn = warp & 1;
    const int tg = lane & 3, gp = lane >> 2;

    const int pt = blockIdx.x * 128;
    const int ot = blockIdx.y * 64;
    const int bb = blockIdx.z;

    const float* xb = x + (size_t)bb * CC * 16384;

    const int p  = tid & 127;
    const int t7 = tid >> 7;
    const int wo = tid >> 3;
    const int cq = tid & 7;

    const int pg0 = pt + p;
    const int oh = pg0 >> 6, ow = pg0 & 63;

    float acc[8][4];
#pragma unroll
    for (int i = 0; i < 8; ++i)
#pragma unroll
        for (int j = 0; j < 4; ++j) acc[i][j] = 0.f;

    for (int kt = 0; kt < 8; ++kt) {
        for (int tap = 0; tap < 9; ++tap) {
            int ti = tap / 3, tj = tap % 3;
            int ih = 2 * oh - 1 + ti;
            int iw = 2 * ow - 1 + tj;
            bool ok = (ih >= 0) && (iw >= 0);
            const float* src = xb + (size_t)(kt * 32) * 16384 + ih * 128 + iw;

            float xr[16];
#pragma unroll
            for (int j = 0; j < 4; ++j) {
                int q = 2 * j + t7;
#pragma unroll
                for (int r = 0; r < 4; ++r) {
                    int kp = q * 4 + r;
                    int k = ((kp & 7) << 2) + (kp >> 3);
                    xr[j * 4 + r] = ok ? __ldg(src + (size_t)k * 16384) : 0.f;
                }
            }
            float wrv[8];
#pragma unroll
            for (int j = 0; j < 2; ++j) {
                int o = j * 32 + wo;
#pragma unroll
                for (int i = 0; i < 4; ++i)
                    wrv[j * 4 + i] = __ldg(
                        &w[((size_t)(ot + o) * CC + kt * 32 + cq * 4 + i) * 9 + ti * 3 + tj]);
            }

#pragma unroll
            for (int j = 0; j < 4; ++j) {
                int q = 2 * j + t7;
                *reinterpret_cast<uint4*>(&Xs[p * PAD + q * 4]) =
                    make_uint4(f2tf32(xr[j * 4]), f2tf32(xr[j * 4 + 1]),
                               f2tf32(xr[j * 4 + 2]), f2tf32(xr[j * 4 + 3]));
            }
#pragma unroll
            for (int j = 0; j < 2; ++j) {
                int o = j * 32 + wo;
#pragma unroll
                for (int i = 0; i < 4; ++i)
                    Ws[o * PAD + i * 8 + cq] = f2tf32(wrv[j * 4 + i]);
            }
            __syncthreads();

            mma_phase<4>(Xs, Ws, acc, wm, wn, tg, gp);
            __syncthreads();
        }
    }

#pragma unroll
    for (int nt = 0; nt < 4; ++nt) {
        int o = ot + wn * 32 + nt * 8 + tg * 2;
        float b0 = __ldg(&bias[o]);
        float b1 = __ldg(&bias[o + 1]);
#pragma unroll
        for (int mt = 0; mt < 2; ++mt) {
#pragma unroll
            for (int hr = 0; hr < 2; ++hr) {
                int pg = pt + wm * 32 + mt * 16 + gp + hr * 8;
                float2 r;
                r.x = acc[mt * 4 + nt][hr * 2 + 0] + b0;
                r.y = acc[mt * 4 + nt][hr * 2 + 1] + b1;
                *reinterpret_cast<float2*>(out + ((size_t)bb * 4096 + pg) * CC + o) = r;
            }
        }
    }
}

extern "C" void kernel_launch(void* const* d_in, const int* in_sizes, int n_in,
                              void* d_out, int out_size) {
    const float* x1 = (const float*)d_in[0];
    const float* x2 = (const float*)d_in[1];
    const float* q1_w = (const float*)d_in[2];
    const float* q1_b = (const float*)d_in[3];
    const float* q2_w = (const float*)d_in[4];
    const float* q2_b = (const float*)d_in[5];
    const float* ks1_w = (const float*)d_in[6];
    const float* ks1_b = (const float*)d_in[7];
    const float* ks2_w = (const float*)d_in[8];
    const float* ks2_b = (const float*)d_in[9];
    const float* kup_w = (const float*)d_in[10];
    const float* kup_b = (const float*)d_in[11];
    const float* v1_w = (const float*)d_in[12];
    const float* v1_b = (const float*)d_in[13];
    const float* v2_w = (const float*)d_in[14];
    const float* v2_b = (const float*)d_in[15];
    const float* kd_w = (const float*)d_in[16];
    const float* kd_b = (const float*)d_in[17];

    float* out = (float*)d_out;
    float* q1  = out;                    // 2*128*128*256
    float* q2  = out + 8388608;          // 2*64*64*256
    float* kup = out + 10485760;         // 2*128*128*256 (upsampled)
    float* ks1 = out + 18874368;
    float* ks2 = out + 27262976;
    float* kdn = out + 29360128;
    float* v1  = out + 31457280;
    float* v2  = out + 39845888;

    ConvSet cs1;
    cs1.w[0] = q1_w;  cs1.b[0] = q1_b;  cs1.out[0] = q1;
    cs1.w[1] = ks1_w; cs1.b[1] = ks1_b; cs1.out[1] = ks1;
    cs1.w[2] = v1_w;  cs1.b[2] = v1_b;  cs1.out[2] = v1;
    cs1.w[3] = q1_w;  cs1.b[3] = q1_b;  cs1.out[3] = q1;  // unused

    ConvSet cs2;
    cs2.w[0] = q2_w;  cs2.b[0] = q2_b;  cs2.out[0] = q2;
    cs2.w[1] = ks2_w; cs2.b[1] = ks2_b; cs2.out[1] = ks2;
    cs2.w[2] = v2_w;  cs2.b[2] = v2_b;  cs2.out[2] = v2;
    cs2.w[3] = kup_w; cs2.b[3] = kup_b; cs2.out[3] = kup;

    static bool attr_done = false;
    if (!attr_done) {
        cudaFuncSetAttribute(conv1x1_cp<-1>,
                             cudaFuncAttributeMaxDynamicSharedMemorySize, SMEM1);
        cudaFuncSetAttribute(conv1x1_cp<3>,
                             cudaFuncAttributeMaxDynamicSharedMemorySize, SMEM1);
        attr_done = true;
    }

    dim3 blk(256);
    conv1x1_cp<-1><<<dim3(128, 6, 2), blk, SMEM1>>>(x1, cs1, 16384);
    conv1x1_cp<3><<<dim3(32, 8, 2), blk, SMEM1>>>(x2, cs2, 4096);
    conv3x3s2_kernel<<<dim3(32, 4, 2), blk>>>(x1, kd_w, kd_b, kdn);
}

// round 13
// speedup vs baseline: 1.3381x; 1.3381x over previous
#include <cuda_runtime.h>
#include <cstdint>

// ---------------------------------------------------------------------------
// FPNAttentionV2: ALL work (7x conv1x1 + conv3x3/s2) in ONE kernel launch.
// Bodies are the proven R6 (382us) implementations; merging removes the two
// inter-kernel tail waves + launch gaps. Deep conv3x3 CTAs scheduled first.
//
// TF32 mma.sync m16n8k8, CTA tile 128px x (128|64)och x BK=32, 256 threads,
// 8 warps 4(M) x 2(N), launch_bounds(256,2) -> 2 CTAs/SM.
// Smem: tile[row][kperm], kperm(k)=(k%4)*8+k/4, stride 36 words ->
// conflict-free LDS.128 fragments / STS.128 stores.
// ---------------------------------------------------------------------------

#define CC 256
#define PAD 36

__device__ __forceinline__ uint32_t f2tf32(float f) {
    uint32_t r;
    asm("cvt.rna.tf32.f32 %0, %1;" : "=r"(r) : "f"(f));
    return r;
}

__device__ __forceinline__ void mma_tf32(float* c, const uint32_t* a, const uint32_t* b) {
    asm volatile(
        "mma.sync.aligned.m16n8k8.row.col.f32.tf32.tf32.f32 "
        "{%0,%1,%2,%3}, {%4,%5,%6,%7}, {%8,%9}, {%0,%1,%2,%3};"
        : "+f"(c[0]), "+f"(c[1]), "+f"(c[2]), "+f"(c[3])
        : "r"(a[0]), "r"(a[1]), "r"(a[2]), "r"(a[3]), "r"(b[0]), "r"(b[1]));
}

// One 128 x (NT*16) x 32 tile MMA phase. acc indexed [mt*NT + nt][4].
template <int NT>
__device__ __forceinline__ void mma_phase(
    const uint32_t* __restrict__ Xp, const uint32_t* __restrict__ Wp,
    float (*acc)[4], int wm, int wn, int tg, int gp) {
#pragma unroll
    for (int h = 0; h < 2; ++h) {
        uint4 af[2][2], bf[NT];
#pragma unroll
        for (int mt = 0; mt < 2; ++mt) {
            int row = wm * 32 + mt * 16 + gp;
            af[mt][0] = *reinterpret_cast<const uint4*>(&Xp[row * PAD + tg * 8 + h * 4]);
            af[mt][1] = *reinterpret_cast<const uint4*>(&Xp[(row + 8) * PAD + tg * 8 + h * 4]);
        }
#pragma unroll
        for (int nt = 0; nt < NT; ++nt) {
            int col = wn * (NT * 8) + nt * 8 + gp;
            bf[nt] = *reinterpret_cast<const uint4*>(&Wp[col * PAD + tg * 8 + h * 4]);
        }
#pragma unroll
        for (int s = 0; s < 2; ++s) {
#pragma unroll
            for (int mt = 0; mt < 2; ++mt) {
                const uint32_t* a0 = reinterpret_cast<const uint32_t*>(&af[mt][0]);
                const uint32_t* a1 = reinterpret_cast<const uint32_t*>(&af[mt][1]);
                uint32_t a[4] = {a0[2 * s], a1[2 * s], a0[2 * s + 1], a1[2 * s + 1]};
#pragma unroll
                for (int nt = 0; nt < NT; ++nt) {
                    const uint32_t* bw = reinterpret_cast<const uint32_t*>(&bf[nt]);
                    uint32_t bq[2] = {bw[2 * s], bw[2 * s + 1]};
                    mma_tf32(acc[mt * NT + nt], a, bq);
                }
            }
        }
    }
}

struct ConvSet {
    const float* w[4];
    const float* b[4];
    float* out[4];
};

struct AllArgs {
    const float* x1;
    const float* x2;
    const float* kd_w;
    const float* kd_b;
    float* kdn;
    ConvSet cs1;
    ConvSet cs2;
};

// ---- conv1x1 body (R6, UPS as runtime flag) -------------------------------
__device__ __forceinline__ void conv1x1_body(
    const float* __restrict__ x, const ConvSet& cs, int HW,
    int bx, int by, int bb, bool ups_mode,
    uint32_t* Xs, uint32_t* Ws) {
    const int tid  = threadIdx.x;
    const int lane = tid & 31;
    const int warp = tid >> 5;
    const int wm = warp >> 1, wn = warp & 1;
    const int tg = lane & 3, gp = lane >> 2;

    const int pt  = bx * 128;
    const int cid = by >> 1;
    const int ot  = (by & 1) * 128;

    const float* xb   = x + (size_t)bb * CC * HW;
    const float* wptr = cs.w[cid];
    const float* bptr = cs.b[cid];
    float* out        = cs.out[cid];

    const int p  = tid & 127;
    const int t7 = tid >> 7;
    const int wo = tid >> 3;
    const int cq = tid & 7;

    float acc[16][4];
#pragma unroll
    for (int i = 0; i < 16; ++i)
#pragma unroll
        for (int j = 0; j < 4; ++j) acc[i][j] = 0.f;

    for (int kt = 0; kt < 8; ++kt) {
        float xr[16];
#pragma unroll
        for (int j = 0; j < 4; ++j) {
            int q = 2 * j + t7;
#pragma unroll
            for (int r = 0; r < 4; ++r) {
                int kp = q * 4 + r;
                int k = ((kp & 7) << 2) + (kp >> 3);
                xr[j * 4 + r] = __ldg(&xb[(size_t)(kt * 32 + k) * HW + pt + p]);
            }
        }
        float4 wr[4];
#pragma unroll
        for (int j = 0; j < 4; ++j)
            wr[j] = *reinterpret_cast<const float4*>(
                wptr + (size_t)(ot + j * 32 + wo) * CC + kt * 32 + cq * 4);

#pragma unroll
        for (int j = 0; j < 4; ++j) {
            int q = 2 * j + t7;
            *reinterpret_cast<uint4*>(&Xs[p * PAD + q * 4]) =
                make_uint4(f2tf32(xr[j * 4]), f2tf32(xr[j * 4 + 1]),
                           f2tf32(xr[j * 4 + 2]), f2tf32(xr[j * 4 + 3]));
        }
#pragma unroll
        for (int j = 0; j < 4; ++j) {
            int o = j * 32 + wo;
            Ws[o * PAD + 0 + cq]  = f2tf32(wr[j].x);
            Ws[o * PAD + 8 + cq]  = f2tf32(wr[j].y);
            Ws[o * PAD + 16 + cq] = f2tf32(wr[j].z);
            Ws[o * PAD + 24 + cq] = f2tf32(wr[j].w);
        }
        __syncthreads();

        mma_phase<8>(Xs, Ws, acc, wm, wn, tg, gp);
        __syncthreads();
    }

#pragma unroll
    for (int nt = 0; nt < 8; ++nt) {
        int o = ot + wn * 64 + nt * 8 + tg * 2;
        float b0 = __ldg(&bptr[o]);
        float b1 = __ldg(&bptr[o + 1]);
#pragma unroll
        for (int mt = 0; mt < 2; ++mt) {
#pragma unroll
            for (int hr = 0; hr < 2; ++hr) {
                int pg = pt + wm * 32 + mt * 16 + gp + hr * 8;
                float2 r;
                r.x = acc[mt * 8 + nt][hr * 2 + 0] + b0;
                r.y = acc[mt * 8 + nt][hr * 2 + 1] + b1;
                if (ups_mode && cid == 3) {
                    int hh = pg >> 6, wc = pg & 63;
                    float* base = out +
                        ((size_t)bb * 16384 + (size_t)(2 * hh) * 128 + 2 * wc) * CC + o;
                    *reinterpret_cast<float2*>(base) = r;
                    *reinterpret_cast<float2*>(base + CC) = r;
                    *reinterpret_cast<float2*>(base + 128 * CC) = r;
                    *reinterpret_cast<float2*>(base + 128 * CC + CC) = r;
                } else {
                    *reinterpret_cast<float2*>(out + ((size_t)bb * HW + pg) * CC + o) = r;
                }
            }
        }
    }
}

// ---- conv3x3/s2 body (R6) -------------------------------------------------
__device__ __forceinline__ void conv3x3_body(
    const float* __restrict__ x, const float* __restrict__ w,
    const float* __restrict__ bias, float* __restrict__ out,
    int bx, int oq, int bb, uint32_t* Xs, uint32_t* Ws) {
    const int tid  = threadIdx.x;
    const int lane = tid & 31;
    const int warp = tid >> 5;
    const int wm = warp >> 1, wn = warp & 1;
    const int tg = lane & 3, gp = lane >> 2;

    const int pt = bx * 128;
    const int ot = oq * 64;

    const float* xb = x + (size_t)bb * CC * 16384;

    const int p  = tid & 127;
    const int t7 = tid >> 7;
    const int wo = tid >> 3;
    const int cq = tid & 7;

    const int pg0 = pt + p;
    const int oh = pg0 >> 6, ow = pg0 & 63;

    float acc[8][4];
#pragma unroll
    for (int i = 0; i < 8; ++i)
#pragma unroll
        for (int j = 0; j < 4; ++j) acc[i][j] = 0.f;

    for (int kt = 0; kt < 8; ++kt) {
        for (int tap = 0; tap < 9; ++tap) {
            int ti = tap / 3, tj = tap % 3;
            int ih = 2 * oh - 1 + ti;
            int iw = 2 * ow - 1 + tj;
            bool ok = (ih >= 0) && (iw >= 0);
            const float* src = xb + (size_t)(kt * 32) * 16384 + ih * 128 + iw;

            float xr[16];
#pragma unroll
            for (int j = 0; j < 4; ++j) {
                int q = 2 * j + t7;
#pragma unroll
                for (int r = 0; r < 4; ++r) {
                    int kp = q * 4 + r;
                    int k = ((kp & 7) << 2) + (kp >> 3);
                    xr[j * 4 + r] = ok ? __ldg(src + (size_t)k * 16384) : 0.f;
                }
            }
            float wrv[8];
#pragma unroll
            for (int j = 0; j < 2; ++j) {
                int o = j * 32 + wo;
#pragma unroll
                for (int i = 0; i < 4; ++i)
                    wrv[j * 4 + i] = __ldg(
                        &w[((size_t)(ot + o) * CC + kt * 32 + cq * 4 + i) * 9 + ti * 3 + tj]);
            }

#pragma unroll
            for (int j = 0; j < 4; ++j) {
                int q = 2 * j + t7;
                *reinterpret_cast<uint4*>(&Xs[p * PAD + q * 4]) =
                    make_uint4(f2tf32(xr[j * 4]), f2tf32(xr[j * 4 + 1]),
                               f2tf32(xr[j * 4 + 2]), f2tf32(xr[j * 4 + 3]));
            }
#pragma unroll
            for (int j = 0; j < 2; ++j) {
                int o = j * 32 + wo;
#pragma unroll
                for (int i = 0; i < 4; ++i)
                    Ws[o * PAD + i * 8 + cq] = f2tf32(wrv[j * 4 + i]);
            }
            __syncthreads();

            mma_phase<4>(Xs, Ws, acc, wm, wn, tg, gp);
            __syncthreads();
        }
    }

#pragma unroll
    for (int nt = 0; nt < 4; ++nt) {
        int o = ot + wn * 32 + nt * 8 + tg * 2;
        float b0 = __ldg(&bias[o]);
        float b1 = __ldg(&bias[o + 1]);
#pragma unroll
        for (int mt = 0; mt < 2; ++mt) {
#pragma unroll
            for (int hr = 0; hr < 2; ++hr) {
                int pg = pt + wm * 32 + mt * 16 + gp + hr * 8;
                float2 r;
                r.x = acc[mt * 4 + nt][hr * 2 + 0] + b0;
                r.y = acc[mt * 4 + nt][hr * 2 + 1] + b1;
                *reinterpret_cast<float2*>(out + ((size_t)bb * 4096 + pg) * CC + o) = r;
            }
        }
    }
}

// ---- the single fused kernel ----------------------------------------------
// CTA ranges: [0,256) conv3x3 (deepest first); [256,1792) x1 convs;
// [1792,2304) x2 convs.
__global__ __launch_bounds__(256, 2) void fused_all(AllArgs A) {
    __shared__ uint32_t Xs[128 * PAD];
    __shared__ uint32_t Ws[128 * PAD];

    const int bid = blockIdx.x;
    if (bid < 256) {
        int t = bid;
        int bx = t & 31; t >>= 5;
        int oq = t & 3;
        int bb = t >> 2;
        conv3x3_body(A.x1, A.kd_w, A.kd_b, A.kdn, bx, oq, bb, Xs, Ws);
    } else if (bid < 1792) {
        int t = bid - 256;
        int bx = t % 128; t /= 128;
        int by = t % 6;
        int bb = t / 6;
        conv1x1_body(A.x1, A.cs1, 16384, bx, by, bb, false, Xs, Ws);
    } else {
        int t = bid - 1792;
        int bx = t & 31; t >>= 5;
        int by = t & 7;
        int bb = t >> 3;
        conv1x1_body(A.x2, A.cs2, 4096, bx, by, bb, true, Xs, Ws);
    }
}

extern "C" void kernel_launch(void* const* d_in, const int* in_sizes, int n_in,
                              void* d_out, int out_size) {
    const float* x1 = (const float*)d_in[0];
    const float* x2 = (const float*)d_in[1];
    const float* q1_w = (const float*)d_in[2];
    const float* q1_b = (const float*)d_in[3];
    const float* q2_w = (const float*)d_in[4];
    const float* q2_b = (const float*)d_in[5];
    const float* ks1_w = (const float*)d_in[6];
    const float* ks1_b = (const float*)d_in[7];
    const float* ks2_w = (const float*)d_in[8];
    const float* ks2_b = (const float*)d_in[9];
    const float* kup_w = (const float*)d_in[10];
    const float* kup_b = (const float*)d_in[11];
    const float* v1_w = (const float*)d_in[12];
    const float* v1_b = (const float*)d_in[13];
    const float* v2_w = (const float*)d_in[14];
    const float* v2_b = (const float*)d_in[15];
    const float* kd_w = (const float*)d_in[16];
    const float* kd_b = (const float*)d_in[17];

    float* out = (float*)d_out;
    float* q1  = out;                    // 2*128*128*256
    float* q2  = out + 8388608;          // 2*64*64*256
    float* kup = out + 10485760;         // 2*128*128*256 (upsampled)
    float* ks1 = out + 18874368;
    float* ks2 = out + 27262976;
    float* kdn = out + 29360128;
    float* v1  = out + 31457280;
    float* v2  = out + 39845888;

    AllArgs A;
    A.x1 = x1; A.x2 = x2; A.kd_w = kd_w; A.kd_b = kd_b; A.kdn = kdn;

    A.cs1.w[0] = q1_w;  A.cs1.b[0] = q1_b;  A.cs1.out[0] = q1;
    A.cs1.w[1] = ks1_w; A.cs1.b[1] = ks1_b; A.cs1.out[1] = ks1;
    A.cs1.w[2] = v1_w;  A.cs1.b[2] = v1_b;  A.cs1.out[2] = v1;
    A.cs1.w[3] = q1_w;  A.cs1.b[3] = q1_b;  A.cs1.out[3] = q1;  // unused

    A.cs2.w[0] = q2_w;  A.cs2.b[0] = q2_b;  A.cs2.out[0] = q2;
    A.cs2.w[1] = ks2_w; A.cs2.b[1] = ks2_b; A.cs2.out[1] = ks2;
    A.cs2.w[2] = v2_w;  A.cs2.b[2] = v2_b;  A.cs2.out[2] = v2;
    A.cs2.w[3] = kup_w; A.cs2.b[3] = kup_b; A.cs2.out[3] = kup;

    fused_all<<<dim3(2304, 1, 1), dim3(256)>>>(A);
}